// round 16
// baseline (speedup 1.0000x reference)
#include <cuda_runtime.h>
#include <cuda_fp16.h>
#include <cstdint>

#define E_TOTAL 160000
#define NNODES  10000
#define NBLK    2500
#define TEDGE   64

#define SP   136
#define SPB  272
#define ABUF (64 * SPB)          // 17408: EA tile (later merge buffer)
#define WBUF (64 * SPB)          // 17408: one n64 x k128 weight chunk

#define EA_OFF  0
#define WB_OFF  ABUF             // 4 contiguous chunk buffers (W1 uses buf0+buf1)
#define FL_OFF  (ABUF + 4*WBUF)  // 87040
#define SSH_B  0                 // f32 [64][4]
#define B1_B   1024              // f32 [128]
#define B2_B   1536              // f32 [1024]
#define A1H_B  5632              // half [64][16] (x0)
#define A3H_B  7680              // half [64][16] (dot/sqrt3)
#define X1H_B  9728              // half [64][48] (x1)
#define DST_B  15872             // int [64]
#define SRC_B  16128             // int [64]
#define FL_SZ  16384
#define SMEM_BYTES (FL_OFF + FL_SZ)   // 103424 -> 2 CTAs/SM

__device__ float g_acc[NNODES * 64];
__device__ float g_cnt[NNODES];
__device__ __align__(16) unsigned char g_w1s[128 * SPB];     // W1T fp16
__device__ __align__(16) unsigned char g_w2s[16][64 * SPB];  // 16 n64-chunks of W2T

__device__ __forceinline__ uint32_t smem_u32(const void* p) {
    uint32_t a;
    asm("{ .reg .u64 t; cvta.to.shared.u64 t, %1; cvt.u32.u64 %0, t; }" : "=r"(a) : "l"(p));
    return a;
}
__device__ __forceinline__ void ldsm_x4(uint32_t* r, uint32_t addr) {
    asm volatile("ldmatrix.sync.aligned.m8n8.x4.shared.b16 {%0,%1,%2,%3}, [%4];"
        : "=r"(r[0]), "=r"(r[1]), "=r"(r[2]), "=r"(r[3]) : "r"(addr));
}
__device__ __forceinline__ void mma16816(float* c, const uint32_t* a, const uint32_t* b) {
    asm volatile("mma.sync.aligned.m16n8k16.row.col.f32.f16.f16.f32 "
        "{%0,%1,%2,%3}, {%4,%5,%6,%7}, {%8,%9}, {%0,%1,%2,%3};"
        : "+f"(c[0]), "+f"(c[1]), "+f"(c[2]), "+f"(c[3])
        : "r"(a[0]), "r"(a[1]), "r"(a[2]), "r"(a[3]), "r"(b[0]), "r"(b[1]));
}
__device__ __forceinline__ uint32_t pkh(float a, float b) {
    __half2 h = __floats2half2_rn(a, b);
    return *(uint32_t*)&h;
}
__device__ __forceinline__ void cp16(uint32_t dst, const void* src) {
    asm volatile("cp.async.cg.shared.global [%0], [%1], 16;" :: "r"(dst), "l"(src));
}
#define CP_COMMIT() asm volatile("cp.async.commit_group;" ::: "memory")
#define CP_WAIT(n)  asm volatile("cp.async.wait_group %0;" :: "n"(n) : "memory")

__global__ void zero_kernel() {
    int i = blockIdx.x * blockDim.x + threadIdx.x;
    if (i < NNODES * 64) g_acc[i] = 0.0f;
    else if (i < NNODES * 64 + NNODES) g_cnt[i - NNODES * 64] = 0.0f;
}

__global__ void prep_w1(const float* __restrict__ w1) {
    int t = blockIdx.x * 256 + threadIdx.x;
    if (t >= 128 * 64) return;
    int h = t >> 6, f = (t & 63) * 2;
    *(uint32_t*)(g_w1s + (uint32_t)h * SPB + (uint32_t)f * 2) =
        pkh(w1[f * 128 + h], w1[(f + 1) * 128 + h]);
}

__global__ void prep_w2(const float* __restrict__ w2) {
    int t = blockIdx.x * 256 + threadIdx.x;
    if (t >= 16 * 64 * 64) return;
    int c = t >> 12, n = (t >> 6) & 63, f = (t & 63) * 2;
    int kg = c * 64 + n;
    *(uint32_t*)(g_w2s[c] + (uint32_t)n * SPB + (uint32_t)f * 2) =
        pkh(w2[f * 1024 + kg], w2[(f + 1) * 1024 + kg]);
}

// ---------------- main fused kernel: 256 threads, 4m x 2kq warp grid ----------------
__global__ void __launch_bounds__(256, 2) fused_kernel(
    const float* __restrict__ x,  const int* __restrict__ ei,
    const float* __restrict__ ea, const float* __restrict__ esh,
    const float* __restrict__ b1, const float* __restrict__ b2)
{
    extern __shared__ unsigned char sm[];
    unsigned char* EAc = sm + EA_OFF;
    unsigned char* FB  = sm + FL_OFF;
    float* Ssh  = (float*)(FB + SSH_B);
    float* b1s  = (float*)(FB + B1_B);
    float* b2s  = (float*)(FB + B2_B);
    __half* Sa1h = (__half*)(FB + A1H_B);
    __half* Sa3h = (__half*)(FB + A3H_B);
    __half* Sx1h = (__half*)(FB + X1H_B);
    int* Sdst = (int*)(FB + DST_B);
    int* Ssrc = (int*)(FB + SRC_B);
    float* Mg = (float*)(sm + EA_OFF);      // merge buffer aliases EA (dead after GEMM1)

    const int tid = threadIdx.x;
    const int wid = tid >> 5, lid = tid & 31;
    const int e0  = blockIdx.x * TEDGE;
    const uint32_t sb = smem_u32(sm);

    const int mg = wid & 3;                 // m-group (16 edges)
    const int kq = wid >> 2;                // c-half / k-split of GEMM2
    const int r0 = mg * 16 + (lid >> 2), r1 = r0 + 8;
    const int cb = (lid & 3) * 2;
    const float kq0f = (kq == 0) ? 1.0f : 0.0f;
    const uint32_t aoff = (uint32_t)(mg * 16 + (lid & 15)) * SPB + (uint32_t)(lid >> 4) * 16;

    // prefetch ring: G0 = W1 (buf0+buf1), G1 = W2[0]->buf2, G2 = W2[1]->buf3
    #pragma unroll
    for (int i = 0; i < 9; i++) {
        uint32_t o = (uint32_t)(tid + i * 256) * 16;
        if (o < 2 * WBUF) cp16(sb + WB_OFF + o, g_w1s + o);
    }
    CP_COMMIT();
    #pragma unroll
    for (int i = 0; i < 5; i++) {
        uint32_t o = (uint32_t)(tid + i * 256) * 16;
        if (o < WBUF) cp16(sb + WB_OFF + 2 * WBUF + o, g_w2s[0] + o);
    }
    CP_COMMIT();
    #pragma unroll
    for (int i = 0; i < 5; i++) {
        uint32_t o = (uint32_t)(tid + i * 256) * 16;
        if (o < WBUF) cp16(sb + WB_OFF + 3 * WBUF + o, g_w2s[1] + o);
    }
    CP_COMMIT();

    // biases + indices + sh
    if (tid < 128) b1s[tid] = b1[tid];
    #pragma unroll
    for (int i = 0; i < 4; i++) b2s[tid + i * 256] = b2[tid + i * 256];
    if (tid < TEDGE) {
        int eg = e0 + tid;
        Ssrc[tid] = ei[eg];
        Sdst[tid] = ei[E_TOTAL + eg];
        float4 s = *(const float4*)(esh + (size_t)eg * 4);
        Ssh[tid*4+0] = s.x; Ssh[tid*4+1] = s.y; Ssh[tid*4+2] = s.z; Ssh[tid*4+3] = s.w;
    }
    __syncthreads();

    // gather x[src] + TP precompute (fp16 tables)
    {
        int e = tid & 63, part = tid >> 6;
        if (part < 2) {
            int src = Ssrc[e];
            const float4* xr = (const float4*)(x + (size_t)src * 64);
            if (part == 0) {
                uint32_t* dst = (uint32_t*)(Sa1h) + e * 8;
                #pragma unroll
                for (int q = 0; q < 4; q++) {
                    float4 xv = xr[q];
                    dst[q*2]     = pkh(xv.x, xv.y);
                    dst[q*2 + 1] = pkh(xv.z, xv.w);
                }
            } else {
                float s1x = Ssh[e*4+1], s1y = Ssh[e*4+2], s1z = Ssh[e*4+3];
                float x1l[48];
                uint32_t* xd = (uint32_t*)(Sx1h) + e * 24;
                #pragma unroll
                for (int q = 0; q < 12; q++) {
                    float4 xv = xr[4 + q];
                    x1l[q*4+0]=xv.x; x1l[q*4+1]=xv.y; x1l[q*4+2]=xv.z; x1l[q*4+3]=xv.w;
                    xd[q*2]     = pkh(xv.x, xv.y);
                    xd[q*2 + 1] = pkh(xv.z, xv.w);
                }
                uint32_t* ad = (uint32_t*)(Sa3h) + e * 8;
                #pragma unroll
                for (int i = 0; i < 8; i++) {
                    float d0 = (x1l[(2*i)*3]*s1x + x1l[(2*i)*3+1]*s1y + x1l[(2*i)*3+2]*s1z)
                               * 0.57735026918962576f;
                    float d1 = (x1l[(2*i+1)*3]*s1x + x1l[(2*i+1)*3+1]*s1y + x1l[(2*i+1)*3+2]*s1z)
                               * 0.57735026918962576f;
                    ad[i] = pkh(d0, d1);
                }
            }
        }
    }

    // EA tile -> fp16 (quarter row per thread)
    {
        int r = tid >> 2, q = tid & 3;
        const float4* rowp = (const float4*)(ea + (size_t)(e0 + r) * 128 + q * 32);
        uint32_t* dst = (uint32_t*)(EAc + (uint32_t)r * SPB + (uint32_t)(q * 32) * 2);
        #pragma unroll
        for (int j = 0; j < 8; j++) {
            float4 v = rowp[j];
            dst[j*2]     = pkh(v.x, v.y);
            dst[j*2 + 1] = pkh(v.z, v.w);
        }
    }

    // GEMM1: H-half (c in [kq*64, kq*64+64)) = EA @ W1-half ; result stays in registers
    CP_WAIT(2);
    __syncthreads();

    float acc1[8][4];
    #pragma unroll
    for (int nt = 0; nt < 8; nt++)
        #pragma unroll
        for (int q = 0; q < 4; q++) acc1[nt][q] = 0.0f;

    {
        uint32_t w1b = sb + WB_OFF + (uint32_t)(kq * 64 + (lid & 7)) * SPB
                     + (uint32_t)(lid >> 3) * 16;
        #pragma unroll
        for (int kp = 0; kp < 4; kp++) {
            uint32_t Am[8];
            ldsm_x4(Am,     sb + EA_OFF + aoff + kp * 64);
            ldsm_x4(Am + 4, sb + EA_OFF + aoff + kp * 64 + 32);
            #pragma unroll
            for (int nt = 0; nt < 8; nt++) {
                uint32_t Bf[4];
                ldsm_x4(Bf, w1b + (uint32_t)nt * (8 * SPB) + kp * 64);
                mma16816(acc1[nt], Am,     Bf);
                mma16816(acc1[nt], Am + 4, Bf + 2);
            }
        }
    }
    __syncthreads();   // EA + W1 buffers free

    // prefetch W2[2]->buf0 (G3), W2[3]->buf1 (G4)
    #pragma unroll
    for (int i = 0; i < 5; i++) {
        uint32_t o = (uint32_t)(tid + i * 256) * 16;
        if (o < WBUF) cp16(sb + WB_OFF + o, g_w2s[2] + o);
    }
    CP_COMMIT();
    #pragma unroll
    for (int i = 0; i < 5; i++) {
        uint32_t o = (uint32_t)(tid + i * 256) * 16;
        if (o < WBUF) cp16(sb + WB_OFF + WBUF + o, g_w2s[3] + o);
    }
    CP_COMMIT();

    // pack H (bias+relu) into A-fragment registers: D-frag == A-frag layout
    uint32_t Hreg[16];
    #pragma unroll
    for (int j = 0; j < 4; j++) {
        int ntA = 2*j, ntB = 2*j + 1;
        float bA0 = b1s[kq*64 + ntA*8 + cb], bA1 = b1s[kq*64 + ntA*8 + cb + 1];
        float bB0 = b1s[kq*64 + ntB*8 + cb], bB1 = b1s[kq*64 + ntB*8 + cb + 1];
        Hreg[4*j+0] = pkh(fmaxf(acc1[ntA][0]+bA0, 0.f), fmaxf(acc1[ntA][1]+bA1, 0.f));
        Hreg[4*j+1] = pkh(fmaxf(acc1[ntA][2]+bA0, 0.f), fmaxf(acc1[ntA][3]+bA1, 0.f));
        Hreg[4*j+2] = pkh(fmaxf(acc1[ntB][0]+bB0, 0.f), fmaxf(acc1[ntB][1]+bB1, 0.f));
        Hreg[4*j+3] = pkh(fmaxf(acc1[ntB][2]+bB0, 0.f), fmaxf(acc1[ntB][3]+bB1, 0.f));
    }

    // GEMM2: 16 n64-chunks, A = Hreg (k-split by kq), B from 4-deep ring
    float s0[2][4], t1[2][4], o1[2][4][3];
    #pragma unroll
    for (int er = 0; er < 2; er++)
        #pragma unroll
        for (int vi = 0; vi < 4; vi++) {
            s0[er][vi] = 0.0f; t1[er][vi] = 0.0f;
            o1[er][vi][0] = 0.0f; o1[er][vi][1] = 0.0f; o1[er][vi][2] = 0.0f;
        }

    const uint32_t bq = (uint32_t)(lid & 7) * SPB + (uint32_t)kq * 128
                      + (uint32_t)(lid >> 3) * 16;

    #pragma unroll 1
    for (int ch = 0; ch < 16; ch++) {
        CP_WAIT(3);         // retires exactly through the group that loaded W2[ch]
        __syncthreads();

        float acc[8][4];
        #pragma unroll
        for (int nt = 0; nt < 8; nt++)
            #pragma unroll
            for (int q = 0; q < 4; q++) acc[nt][q] = 0.0f;

        uint32_t wb = sb + WB_OFF + (uint32_t)((ch + 2) & 3) * WBUF + bq;
        #pragma unroll
        for (int kp2 = 0; kp2 < 2; kp2++) {
            #pragma unroll
            for (int nt = 0; nt < 8; nt++) {
                uint32_t Bf[4];
                ldsm_x4(Bf, wb + (uint32_t)nt * (8 * SPB) + kp2 * 64);
                mma16816(acc[nt], Hreg + kp2*8,     Bf);
                mma16816(acc[nt], Hreg + kp2*8 + 4, Bf + 2);
            }
        }

        // TP: k = ch*64 + nt*8 + cb + d ; p = ch>>2 ; u = (ch&3)*4 + (nt>>1) ; v = (nt&1)*8+cb+d
        const int p  = ch >> 2;
        const int ub = (ch & 3) * 4;
        const float* b2c = b2s + ch * 64;

        if (p == 2) {
            #pragma unroll
            for (int nt = 0; nt < 8; nt++) {
                int u = ub + (nt >> 1);
                float xa0 = __half2float(Sx1h[r0*48 + u*3 + 0]);
                float xb0 = __half2float(Sx1h[r0*48 + u*3 + 1]);
                float xc0 = __half2float(Sx1h[r0*48 + u*3 + 2]);
                float xa1 = __half2float(Sx1h[r1*48 + u*3 + 0]);
                float xb1 = __half2float(Sx1h[r1*48 + u*3 + 1]);
                float xc1 = __half2float(Sx1h[r1*48 + u*3 + 2]);
                #pragma unroll
                for (int d = 0; d < 2; d++) {
                    float bb = b2c[nt*8 + cb + d] * kq0f;
                    int vi = (nt & 1) * 2 + d;
                    float w0 = acc[nt][d]     + bb;
                    float w1 = acc[nt][2 + d] + bb;
                    o1[0][vi][0] = fmaf(xa0, w0, o1[0][vi][0]);
                    o1[0][vi][1] = fmaf(xb0, w0, o1[0][vi][1]);
                    o1[0][vi][2] = fmaf(xc0, w0, o1[0][vi][2]);
                    o1[1][vi][0] = fmaf(xa1, w1, o1[1][vi][0]);
                    o1[1][vi][1] = fmaf(xb1, w1, o1[1][vi][1]);
                    o1[1][vi][2] = fmaf(xc1, w1, o1[1][vi][2]);
                }
            }
        } else {
            float a0[4], a1[4];
            if (p == 0) {
                float sh0a = Ssh[r0*4], sh0b = Ssh[r1*4];
                #pragma unroll
                for (int u = 0; u < 4; u++) {
                    a0[u] = __half2float(Sa1h[r0*16 + ub + u]) * sh0a;
                    a1[u] = __half2float(Sa1h[r1*16 + ub + u]) * sh0b;
                }
            } else {
                const __half* A = (p == 1) ? Sa1h : Sa3h;
                #pragma unroll
                for (int u = 0; u < 4; u++) {
                    a0[u] = __half2float(A[r0*16 + ub + u]);
                    a1[u] = __half2float(A[r1*16 + ub + u]);
                }
            }
            if (p == 1) {
                #pragma unroll
                for (int nt = 0; nt < 8; nt++) {
                    int u = nt >> 1;
                    #pragma unroll
                    for (int d = 0; d < 2; d++) {
                        float bb = b2c[nt*8 + cb + d] * kq0f;
                        int vi = (nt & 1) * 2 + d;
                        t1[0][vi] = fmaf(a0[u], acc[nt][d]     + bb, t1[0][vi]);
                        t1[1][vi] = fmaf(a1[u], acc[nt][2 + d] + bb, t1[1][vi]);
                    }
                }
            } else {
                #pragma unroll
                for (int nt = 0; nt < 8; nt++) {
                    int u = nt >> 1;
                    #pragma unroll
                    for (int d = 0; d < 2; d++) {
                        float bb = b2c[nt*8 + cb + d] * kq0f;
                        int vi = (nt & 1) * 2 + d;
                        s0[0][vi] = fmaf(a0[u], acc[nt][d]     + bb, s0[0][vi]);
                        s0[1][vi] = fmaf(a1[u], acc[nt][2 + d] + bb, s0[1][vi]);
                    }
                }
            }
        }
        __syncthreads();   // buffer reads done before refill

        // refill buffer just read with W2[ch+4]; ALWAYS commit (empty groups keep ring math)
        if (ch + 4 <= 15) {
            const unsigned char* s2 = g_w2s[ch + 4];
            uint32_t dsto = WB_OFF + (uint32_t)((ch + 2) & 3) * WBUF;
            #pragma unroll
            for (int i = 0; i < 5; i++) {
                uint32_t o = (uint32_t)(tid + i * 256) * 16;
                if (o < WBUF) cp16(sb + dsto + o, s2 + o);
            }
        }
        CP_COMMIT();
    }

    // 2-way kq merge in SMEM (Mg aliases EA buffer), then scatter-add
    {
        if (kq == 0) {
            #pragma unroll
            for (int er = 0; er < 2; er++) {
                int e = er ? r1 : r0;
                float sh0 = Ssh[e*4+0];
                float s1x = Ssh[e*4+1], s1y = Ssh[e*4+2], s1z = Ssh[e*4+3];
                float* mrow = Mg + e * 64;
                #pragma unroll
                for (int vi = 0; vi < 4; vi++) {
                    int v = cb + (vi >> 1) * 8 + (vi & 1);
                    mrow[v]            = s0[er][vi];
                    mrow[16 + v*3 + 0] = t1[er][vi]*s1x + sh0*o1[er][vi][0];
                    mrow[16 + v*3 + 1] = t1[er][vi]*s1y + sh0*o1[er][vi][1];
                    mrow[16 + v*3 + 2] = t1[er][vi]*s1z + sh0*o1[er][vi][2];
                }
            }
        }
        __syncthreads();
        if (kq == 1) {
            const float alpha = 0.17677669529663689f;  // 1/sqrt(2*16)
            #pragma unroll
            for (int er = 0; er < 2; er++) {
                int e = er ? r1 : r0;
                int dst = Sdst[e];
                float sh0 = Ssh[e*4+0];
                float s1x = Ssh[e*4+1], s1y = Ssh[e*4+2], s1z = Ssh[e*4+3];
                float* mrow = Mg + e * 64;
                float* base = g_acc + (size_t)dst * 64;
                #pragma unroll
                for (int vi = 0; vi < 4; vi++) {
                    int v = cb + (vi >> 1) * 8 + (vi & 1);
                    atomicAdd(base + v, alpha * (s0[er][vi] + mrow[v]));
                    atomicAdd(base + 16 + v*3 + 0,
                        alpha * (t1[er][vi]*s1x + sh0*o1[er][vi][0] + mrow[16 + v*3 + 0]));
                    atomicAdd(base + 16 + v*3 + 1,
                        alpha * (t1[er][vi]*s1y + sh0*o1[er][vi][1] + mrow[16 + v*3 + 1]));
                    atomicAdd(base + 16 + v*3 + 2,
                        alpha * (t1[er][vi]*s1z + sh0*o1[er][vi][2] + mrow[16 + v*3 + 2]));
                }
                if ((lid & 3) == 0) atomicAdd(&g_cnt[dst], 1.0f);
            }
        }
    }
}

__global__ void finalize_kernel(const float* __restrict__ x, float* __restrict__ out) {
    int i = blockIdx.x * blockDim.x + threadIdx.x;
    if (i < NNODES * 64) {
        int node = i >> 6;
        out[i] = g_acc[i] / fmaxf(g_cnt[node], 1.0f) + x[i];
    }
}

extern "C" void kernel_launch(void* const* d_in, const int* in_sizes, int n_in,
                              void* d_out, int out_size)
{
    const float* x   = (const float*)d_in[0];
    const int*   ei  = (const int*)  d_in[1];
    const float* ea  = (const float*)d_in[2];
    const float* esh = (const float*)d_in[3];
    const float* w1  = (const float*)d_in[4];
    const float* b1  = (const float*)d_in[5];
    const float* w2  = (const float*)d_in[6];
    const float* b2  = (const float*)d_in[7];
    float* out = (float*)d_out;

    cudaFuncSetAttribute(fused_kernel,
                         cudaFuncAttributeMaxDynamicSharedMemorySize, SMEM_BYTES);

    int ztot = NNODES * 64 + NNODES;
    zero_kernel<<<(ztot + 255) / 256, 256>>>();
    prep_w1<<<(128 * 64 + 255) / 256, 256>>>(w1);
    prep_w2<<<(16 * 64 * 64 + 255) / 256, 256>>>(w2);
    fused_kernel<<<NBLK, 256, SMEM_BYTES>>>(x, ei, ea, esh, b1, b2);
    finalize_kernel<<<(NNODES * 64 + 255) / 256, 256>>>(x, out);
}